// round 2
// baseline (speedup 1.0000x reference)
#include <cuda_runtime.h>

#define BSZ  256
#define FDIM 128
#define DDIM 512
#define HH   8
#define HD   64
#define KTOP 64

// ---------------- scratch (device globals: allocation-free) ----------------
__device__ float g_q[BSZ * HH * FDIM * HD];     // (B,H,F,HD)
__device__ float g_k[BSZ * HH * FDIM * HD];
__device__ float g_v[BSZ * HH * FDIM * HD];
__device__ float g_attn[BSZ * FDIM * DDIM];     // (B,F,D)
__device__ float g_pv[BSZ];

// monotone float<->uint key mapping (larger key <=> larger float)
__device__ __forceinline__ unsigned f2k(float f) {
    unsigned u = __float_as_uint(f);
    return (u & 0x80000000u) ? ~u : (u | 0x80000000u);
}
__device__ __forceinline__ float k2f(unsigned k) {
    unsigned u = (k & 0x80000000u) ? (k ^ 0x80000000u) : ~k;
    return __uint_as_float(u);
}

// ---------------- pv gating MLP: one block per batch ----------------
__global__ void __launch_bounds__(256) pv_kernel(
    const float* __restrict__ x,
    const float* __restrict__ W1, const float* __restrict__ b1,
    const float* __restrict__ W2, const float* __restrict__ b2)
{
    int b = blockIdx.x;
    int tid = threadIdx.x;
    __shared__ float comb[1024];
    __shared__ float red[256];

    // price/vol means over F halves
    for (int d = tid; d < DDIM; d += 256) {
        float s1 = 0.f, s2 = 0.f;
        const float* xb = x + (size_t)b * FDIM * DDIM;
        for (int f = 0; f < 64; f++)  s1 += xb[f * DDIM + d];
        for (int f = 64; f < 128; f++) s2 += xb[f * DDIM + d];
        comb[d]       = s1 * (1.f / 64.f);
        comb[512 + d] = s2 * (1.f / 64.f);
    }
    __syncthreads();

    float part = 0.f;
    for (int j = tid; j < DDIM; j += 256) {
        float acc = b1[j];
        for (int i = 0; i < 1024; i++) acc += comb[i] * W1[i * DDIM + j];
        float hsil = acc / (1.f + __expf(-acc));   // silu
        part += hsil * W2[j];
    }
    red[tid] = part;
    for (int s = 128; s > 0; s >>= 1) {
        __syncthreads();
        if (tid < s) red[tid] += red[tid + s];
    }
    __syncthreads();
    if (tid == 0) {
        float z = red[0] + b2[0];
        g_pv[b] = 1.f / (1.f + __expf(-z));
    }
}

// ---------------- q/k/v projection GEMM: 128x128x16 tiles ----------------
// C(z) written in (B,H,F,HD) layout, bias fused.
__global__ void __launch_bounds__(256) qkv_gemm(
    const float* __restrict__ A,
    const float* __restrict__ Wq, const float* __restrict__ Wk, const float* __restrict__ Wv,
    const float* __restrict__ bq, const float* __restrict__ bk, const float* __restrict__ bv)
{
    __shared__ float As[16][128];
    __shared__ float Bs[16][128];

    const float* W; const float* bias; float* C;
    if (blockIdx.z == 0)      { W = Wq; bias = bq; C = g_q; }
    else if (blockIdx.z == 1) { W = Wk; bias = bk; C = g_k; }
    else                      { W = Wv; bias = bv; C = g_v; }

    int tid = threadIdx.x;
    int tx = tid & 15, ty = tid >> 4;
    int bm = blockIdx.x * 128;
    int bn = blockIdx.y * 128;

    float acc[8][8];
#pragma unroll
    for (int i = 0; i < 8; i++)
#pragma unroll
        for (int j = 0; j < 8; j++) acc[i][j] = 0.f;

    int am = tid >> 2;             // 0..63
    int ac = (tid & 3) << 2;       // 0,4,8,12

    for (int kk = 0; kk < DDIM; kk += 16) {
#pragma unroll
        for (int half = 0; half < 2; half++) {
            int m = am + half * 64;
            float4 t = *(const float4*)(A + (size_t)(bm + m) * DDIM + kk + ac);
            As[ac + 0][m] = t.x; As[ac + 1][m] = t.y;
            As[ac + 2][m] = t.z; As[ac + 3][m] = t.w;
        }
#pragma unroll
        for (int half = 0; half < 2; half++) {
            int idx = tid + half * 256;
            int k = idx >> 5; int c = (idx & 31) << 2;
            *(float4*)(&Bs[k][c]) = *(const float4*)(W + (size_t)(kk + k) * DDIM + bn + c);
        }
        __syncthreads();
#pragma unroll
        for (int k = 0; k < 16; k++) {
            float a[8], bb[8];
#pragma unroll
            for (int i = 0; i < 8; i++) a[i] = As[k][ty * 8 + i];
#pragma unroll
            for (int j = 0; j < 8; j++) bb[j] = Bs[k][tx * 8 + j];
#pragma unroll
            for (int i = 0; i < 8; i++)
#pragma unroll
                for (int j = 0; j < 8; j++) acc[i][j] += a[i] * bb[j];
        }
        __syncthreads();
    }

#pragma unroll
    for (int i = 0; i < 8; i++) {
        int gm = bm + ty * 8 + i;
        int bb = gm >> 7, f = gm & 127;
#pragma unroll
        for (int j = 0; j < 8; j++) {
            int gn = bn + tx * 8 + j;
            int hh = gn >> 6, hd = gn & 63;
            C[(((size_t)bb * HH + hh) * FDIM + f) * HD + hd] = acc[i][j] + bias[gn];
        }
    }
}

// ---------------- output projection GEMM (standard row-major out) ----------------
__global__ void __launch_bounds__(256) out_gemm(
    const float* __restrict__ Wo, const float* __restrict__ bo,
    float* __restrict__ Cout)
{
    __shared__ float As[16][128];
    __shared__ float Bs[16][128];
    const float* A = g_attn;

    int tid = threadIdx.x;
    int tx = tid & 15, ty = tid >> 4;
    int bm = blockIdx.x * 128;
    int bn = blockIdx.y * 128;

    float acc[8][8];
#pragma unroll
    for (int i = 0; i < 8; i++)
#pragma unroll
        for (int j = 0; j < 8; j++) acc[i][j] = 0.f;

    int am = tid >> 2;
    int ac = (tid & 3) << 2;

    for (int kk = 0; kk < DDIM; kk += 16) {
#pragma unroll
        for (int half = 0; half < 2; half++) {
            int m = am + half * 64;
            float4 t = *(const float4*)(A + (size_t)(bm + m) * DDIM + kk + ac);
            As[ac + 0][m] = t.x; As[ac + 1][m] = t.y;
            As[ac + 2][m] = t.z; As[ac + 3][m] = t.w;
        }
#pragma unroll
        for (int half = 0; half < 2; half++) {
            int idx = tid + half * 256;
            int k = idx >> 5; int c = (idx & 31) << 2;
            *(float4*)(&Bs[k][c]) = *(const float4*)(Wo + (size_t)(kk + k) * DDIM + bn + c);
        }
        __syncthreads();
#pragma unroll
        for (int k = 0; k < 16; k++) {
            float a[8], bb[8];
#pragma unroll
            for (int i = 0; i < 8; i++) a[i] = As[k][ty * 8 + i];
#pragma unroll
            for (int j = 0; j < 8; j++) bb[j] = Bs[k][tx * 8 + j];
#pragma unroll
            for (int i = 0; i < 8; i++)
#pragma unroll
                for (int j = 0; j < 8; j++) acc[i][j] += a[i] * bb[j];
        }
        __syncthreads();
    }

#pragma unroll
    for (int i = 0; i < 8; i++) {
        int gm = bm + ty * 8 + i;
#pragma unroll
        for (int j = 0; j < 8; j++) {
            int gn = bn + tx * 8 + j;
            Cout[(size_t)gm * DDIM + gn] = acc[i][j] + bo[gn];
        }
    }
}

// ---------------- fused attention: one CTA per (b,h) ----------------
// smem: scores 128x129 (padded) + kv 128x64, dynamic = 98816 bytes
#define SMEM_ATTN ((128 * 129 + 128 * 64) * 4)

__global__ void __launch_bounds__(128) attn_kernel(
    const float* __restrict__ corr,
    const float* __restrict__ fimp)
{
    extern __shared__ float sm[];
    float*    sc  = sm;                       // 128*129 floats (scores / keys / probs)
    unsigned* scu = (unsigned*)sm;
    float*    kv  = sm + 128 * 129;           // 128*64 floats (k tile, then v tile)

    int bh = blockIdx.x;
    int b = bh >> 3, h = bh & 7;
    int r = threadIdx.x;

    // load K tile
    float4* kv4 = (float4*)kv;
    const float4* kb4 = (const float4*)(g_k + (size_t)bh * (FDIM * HD));
    for (int i = r; i < FDIM * HD / 4; i += 128) kv4[i] = kb4[i];

    // load this thread's q row into registers
    float qr[HD];
    const float* qrow = g_q + (size_t)bh * (FDIM * HD) + r * HD;
#pragma unroll
    for (int d = 0; d < HD; d += 4) {
        float4 t = *(const float4*)(qrow + d);
        qr[d] = t.x; qr[d + 1] = t.y; qr[d + 2] = t.z; qr[d + 3] = t.w;
    }
    __syncthreads();

    float fi_r = fimp[r];
    float pvh  = g_pv[b] * 0.5f;
    bool  rlo  = (r < 64);
    const float* crow = corr + r * FDIM;
    unsigned* srow = scu + r * 129;

    // scores: q_r . k_j  (2 rows of K per iteration, 2 chains each)
    for (int j = 0; j < FDIM; j += 2) {
        const float* k0 = kv + j * HD;
        const float* k1 = k0 + HD;
        float a00 = 0.f, a01 = 0.f, a10 = 0.f, a11 = 0.f;
#pragma unroll
        for (int d = 0; d < HD; d += 2) {
            a00 += qr[d] * k0[d];     a01 += qr[d + 1] * k0[d + 1];
            a10 += qr[d] * k1[d];     a11 += qr[d + 1] * k1[d + 1];
        }
        float s0 = (a00 + a01) * 0.125f + crow[j]     * fi_r * fimp[j];
        float s1 = (a10 + a11) * 0.125f + crow[j + 1] * fi_r * fimp[j + 1];
        if (rlo != (j < 64))       s0 += pvh;
        if (rlo != ((j + 1) < 64)) s1 += pvh;
        srow[j]     = f2k(s0);
        srow[j + 1] = f2k(s1);
    }
    __syncthreads();   // all threads done reading K tile

    // overwrite kv with V tile (selection below only touches own score row)
    const float4* vb4 = (const float4*)(g_v + (size_t)bh * (FDIM * HD));
    for (int i = r; i < FDIM * HD / 4; i += 128) kv4[i] = vb4[i];

    // exact 64th-largest via MSB-first radix select on keys
    unsigned prefix = 0u;
    int kk = KTOP;
    for (int bit = 31; bit >= 0; --bit) {
        unsigned want = (prefix >> bit) | 1u;
        int c = 0;
#pragma unroll 4
        for (int j = 0; j < FDIM; j++) c += (int)((srow[j] >> bit) == want);
        if (c >= kk) prefix |= (1u << bit); else kk -= c;
    }

    // softmax (masked below threshold; -1e9 entries underflow to 0 in ref too)
    unsigned umax = 0u;
#pragma unroll 4
    for (int j = 0; j < FDIM; j++) umax = max(umax, srow[j]);
    float m = k2f(umax);

    float ssum = 0.f;
    float* frow = sc + r * 129;
    for (int j = 0; j < FDIM; j++) {
        unsigned key = srow[j];
        float e = (key >= prefix) ? __expf(k2f(key) - m) : 0.f;
        frow[j] = e;
        ssum += e;
    }
    float inv = 1.f / ssum;

    __syncthreads();   // V tile fully loaded

    // out_r = (1/ssum) * sum_j e_j * v_j   (64 independent accumulator chains)
    float acc[HD];
#pragma unroll
    for (int d = 0; d < HD; d++) acc[d] = 0.f;
    for (int j = 0; j < FDIM; j++) {
        float e = frow[j];
        const float* vr = kv + j * HD;
#pragma unroll
        for (int d = 0; d < HD; d++) acc[d] += e * vr[d];
    }

    float* obase = g_attn + ((size_t)b * FDIM + r) * DDIM + h * HD;
#pragma unroll
    for (int d = 0; d < HD; d += 4) {
        float4 t;
        t.x = acc[d] * inv; t.y = acc[d + 1] * inv;
        t.z = acc[d + 2] * inv; t.w = acc[d + 3] * inv;
        *(float4*)(obase + d) = t;
    }
}

// ---------------- launch ----------------
extern "C" void kernel_launch(void* const* d_in, const int* in_sizes, int n_in,
                              void* d_out, int out_size)
{
    const float* x    = (const float*)d_in[0];
    const float* Wq   = (const float*)d_in[1];
    const float* bq   = (const float*)d_in[2];
    const float* Wk   = (const float*)d_in[3];
    const float* bk   = (const float*)d_in[4];
    const float* Wv   = (const float*)d_in[5];
    const float* bv   = (const float*)d_in[6];
    const float* Wo   = (const float*)d_in[7];
    const float* bo   = (const float*)d_in[8];
    const float* corr = (const float*)d_in[9];
    const float* fimp = (const float*)d_in[10];
    const float* W1   = (const float*)d_in[11];
    const float* b1   = (const float*)d_in[12];
    const float* W2   = (const float*)d_in[13];
    const float* b2   = (const float*)d_in[14];
    float* out = (float*)d_out;

    cudaFuncSetAttribute(attn_kernel, cudaFuncAttributeMaxDynamicSharedMemorySize, SMEM_ATTN);

    pv_kernel<<<BSZ, 256>>>(x, W1, b1, W2, b2);
    qkv_gemm<<<dim3(256, 4, 3), 256>>>(x, Wq, Wk, Wv, bq, bk, bv);
    attn_kernel<<<BSZ * HH, 128, SMEM_ATTN>>>(corr, fimp);
    out_gemm<<<dim3(256, 4), 256>>>(Wo, bo, out);
}

// round 6
// speedup vs baseline: 1.3598x; 1.3598x over previous
#include <cuda_runtime.h>
#include <cuda_fp16.h>
#include <cstdint>

#define BSZ  256
#define FDIM 128
#define DDIM 512
#define HH   8
#define HD   64
#define KTOP 64
#define MTOT (BSZ * FDIM)            // 32768
#define LOSCALE 2048.0f
#define INVLOSCALE (1.0f / 2048.0f)

// ---------------- scratch (device globals: allocation-free) ----------------
__device__ float g_qkv[(size_t)3 * MTOT * DDIM];   // q,k,v in (B,F,D) plain layout
__device__ float g_attn[(size_t)MTOT * DDIM];      // attention output (B,F,D)
__device__ float g_pv[BSZ];
__device__ __half g_xhi[(size_t)MTOT * DDIM];
__device__ __half g_xlo[(size_t)MTOT * DDIM];      // scaled by 2048
__device__ __half g_ahi[(size_t)MTOT * DDIM];
__device__ __half g_alo[(size_t)MTOT * DDIM];      // scaled by 2048
__device__ __half g_wthi[(size_t)4 * DDIM * DDIM]; // W^T (n,k) for q,k,v,o
__device__ __half g_wtlo[(size_t)4 * DDIM * DDIM]; // scaled by 2048

// ---------------- helpers ----------------
__device__ __forceinline__ uint32_t smem_u32(const void* p) {
    uint32_t a;
    asm("{ .reg .u64 t; cvta.to.shared.u64 t, %1; cvt.u32.u64 %0, t; }" : "=r"(a) : "l"(p));
    return a;
}
__device__ __forceinline__ void cp_async16(uint32_t dst, const void* src) {
    asm volatile("cp.async.cg.shared.global [%0], [%1], 16;" :: "r"(dst), "l"(src) : "memory");
}
__device__ __forceinline__ void cp_commit() {
    asm volatile("cp.async.commit_group;" ::: "memory");
}
template<int N>
__device__ __forceinline__ void cp_wait() {
    asm volatile("cp.async.wait_group %0;" :: "n"(N) : "memory");
}
__device__ __forceinline__ void ldm_x4(uint32_t* r, uint32_t addr) {
    asm volatile("ldmatrix.sync.aligned.m8n8.x4.shared.b16 {%0,%1,%2,%3}, [%4];"
                 : "=r"(r[0]), "=r"(r[1]), "=r"(r[2]), "=r"(r[3]) : "r"(addr));
}
__device__ __forceinline__ void mma16816(float* c, const uint32_t* a, uint32_t b0, uint32_t b1) {
    asm volatile(
        "mma.sync.aligned.m16n8k16.row.col.f32.f16.f16.f32 "
        "{%0,%1,%2,%3}, {%4,%5,%6,%7}, {%8,%9}, {%0,%1,%2,%3};"
        : "+f"(c[0]), "+f"(c[1]), "+f"(c[2]), "+f"(c[3])
        : "r"(a[0]), "r"(a[1]), "r"(a[2]), "r"(a[3]), "r"(b0), "r"(b1));
}

// monotone float<->uint key mapping (larger key <=> larger float)
__device__ __forceinline__ unsigned f2k(float f) {
    unsigned u = __float_as_uint(f);
    return (u & 0x80000000u) ? ~u : (u | 0x80000000u);
}
__device__ __forceinline__ float k2f(unsigned k) {
    unsigned u = (k & 0x80000000u) ? (k ^ 0x80000000u) : ~k;
    return __uint_as_float(u);
}

// ---------------- fp16 hi/lo split (lo scaled by 2048) ----------------
// mode 0: src = x param -> g_xhi/g_xlo ; mode 1: src = g_attn -> g_ahi/g_alo
__global__ void __launch_bounds__(256) split_kernel(const float4* __restrict__ xsrc, int mode) {
    size_t i = (size_t)blockIdx.x * 256 + threadIdx.x;   // grid sized exactly
    const float4* src = (mode == 0) ? xsrc : (const float4*)g_attn;
    __half2* hi = (__half2*)((mode == 0) ? g_xhi : g_ahi);
    __half2* lo = (__half2*)((mode == 0) ? g_xlo : g_alo);
    float4 v = src[i];
    __half hx = __float2half(v.x), hy = __float2half(v.y);
    __half hz = __float2half(v.z), hw = __float2half(v.w);
    __half2 h0; h0.x = hx; h0.y = hy;
    __half2 h1; h1.x = hz; h1.y = hw;
    __half2 l0, l1;
    l0.x = __float2half((v.x - __half2float(hx)) * LOSCALE);
    l0.y = __float2half((v.y - __half2float(hy)) * LOSCALE);
    l1.x = __float2half((v.z - __half2float(hz)) * LOSCALE);
    l1.y = __float2half((v.w - __half2float(hw)) * LOSCALE);
    hi[2 * i] = h0; hi[2 * i + 1] = h1;
    lo[2 * i] = l0; lo[2 * i + 1] = l1;
}

// ---------------- weight transpose + split: W[k][n] -> Wt[n][k] hi/lo ----------------
__global__ void wsplit_kernel(const float* __restrict__ Wq, const float* __restrict__ Wk,
                              const float* __restrict__ Wv, const float* __restrict__ Wo) {
    int z = blockIdx.z;
    const float* W = (z == 0) ? Wq : (z == 1) ? Wk : (z == 2) ? Wv : Wo;
    __shared__ float t[32][33];
    int n0 = blockIdx.x * 32, k0 = blockIdx.y * 32;
    int tx = threadIdx.x, ty = threadIdx.y;
    t[ty][tx] = W[(size_t)(k0 + ty) * DDIM + n0 + tx];
    __syncthreads();
    float v = t[tx][ty];                      // = W[k0+tx][n0+ty]
    __half h = __float2half(v);
    size_t o = (size_t)z * DDIM * DDIM + (size_t)(n0 + ty) * DDIM + k0 + tx;
    g_wthi[o] = h;
    g_wtlo[o] = __float2half((v - __half2float(h)) * LOSCALE);
}

// ---------------- pv gating MLP: one block per batch ----------------
__global__ void __launch_bounds__(256) pv_kernel(
    const float* __restrict__ x,
    const float* __restrict__ W1, const float* __restrict__ b1,
    const float* __restrict__ W2, const float* __restrict__ b2)
{
    int b = blockIdx.x;
    int tid = threadIdx.x;
    __shared__ float comb[1024];
    __shared__ float red[256];

    for (int d = tid; d < DDIM; d += 256) {
        float s1 = 0.f, s2 = 0.f;
        const float* xb = x + (size_t)b * FDIM * DDIM;
        for (int f = 0; f < 64; f++)   s1 += xb[f * DDIM + d];
        for (int f = 64; f < 128; f++) s2 += xb[f * DDIM + d];
        comb[d]       = s1 * (1.f / 64.f);
        comb[512 + d] = s2 * (1.f / 64.f);
    }
    __syncthreads();

    float part = 0.f;
    for (int j = tid; j < DDIM; j += 256) {
        float acc = b1[j];
        for (int i = 0; i < 1024; i++) acc += comb[i] * W1[i * DDIM + j];
        float hsil = acc / (1.f + __expf(-acc));
        part += hsil * W2[j];
    }
    red[tid] = part;
    for (int s = 128; s > 0; s >>= 1) {
        __syncthreads();
        if (tid < s) red[tid] += red[tid + s];
    }
    __syncthreads();
    if (tid == 0) {
        float z = red[0] + b2[0];
        g_pv[b] = 1.f / (1.f + __expf(-z));
    }
}

// ---------------- HMMA fp16 4-term split GEMM: C[M,512] = A[M,512] @ W + bias ----------------
// Pass order over virtual K' = 4*512 with scaled residuals (lo' = lo*2048):
//   chunks  0-15 : Alo'*Blo'   (acc = 2^22 AloBlo)
//   rescale acc *= 2^-11
//   chunks 16-31 : Ahi *Blo'   \  (adds 2^11-scaled cross terms)
//   chunks 32-47 : Alo'*Bhi    /
//   rescale acc *= 2^-11
//   chunks 48-63 : Ahi *Bhi
// => exact A*B up to fp32 accumulation rounding.
// CTA: 128x128, 8 warps of 32x64. K-chunk 32, cp.async double buffer.
// smem rows stride 40 halves (80B) -> conflict-free ldmatrix.
#define KC      32
#define ROWH    40
#define NCHUNK  64

__global__ void __launch_bounds__(256, 2) gemm_mma(
    int mode,
    const float* __restrict__ b0, const float* __restrict__ b1, const float* __restrict__ b2,
    float* __restrict__ Cout)
{
    __shared__ __half sA[2][128 * ROWH];
    __shared__ __half sB[2][128 * ROWH];

    int tid  = threadIdx.x;
    int lane = tid & 31;
    int wid  = tid >> 5;
    int wm   = wid & 3;          // 0..3 -> M offset 32*wm
    int wn   = wid >> 2;         // 0..1 -> N offset 64*wn
    int z    = blockIdx.z;

    const __half* Ahi = mode ? g_ahi : g_xhi;
    const __half* Alo = mode ? g_alo : g_xlo;
    int wz = mode ? 3 : z;
    const __half* Bhi = g_wthi + (size_t)wz * DDIM * DDIM;
    const __half* Blo = g_wtlo + (size_t)wz * DDIM * DDIM;
    const float* bias = (z == 0) ? b0 : (z == 1) ? b1 : b2;
    float* C = mode ? Cout : (g_qkv + (size_t)z * MTOT * DDIM);

    int bm = blockIdx.y * 128;
    int bn = blockIdx.x * 128;

    int lrow0 = tid >> 2;              // 0..63
    int lseg  = tid & 3;               // 16B segment within 64B row-chunk

    float acc[2][8][4];
#pragma unroll
    for (int mi = 0; mi < 2; mi++)
#pragma unroll
        for (int nj = 0; nj < 8; nj++)
#pragma unroll
            for (int q = 0; q < 4; q++) acc[mi][nj][q] = 0.f;

    uint32_t sAu[2] = { smem_u32(sA[0]), smem_u32(sA[1]) };
    uint32_t sBu[2] = { smem_u32(sB[0]), smem_u32(sB[1]) };

    // ---- issue loads for a chunk ----
    auto issue = [&](int cc) {
        int p  = cc >> 4;                      // 0:lo*lo 1:hi*lo 2:lo*hi 3:hi*hi
        int k0 = (cc & 15) * KC;
        const __half* As = (p == 0 || p == 2) ? Alo : Ahi;
        const __half* Bs = (p <= 1) ? Blo : Bhi;
        int buf = cc & 1;
#pragma unroll
        for (int r = 0; r < 2; r++) {
            int row = lrow0 + r * 64;
            uint32_t so = (uint32_t)(row * ROWH + lseg * 8) * 2;
            cp_async16(sAu[buf] + so, As + (size_t)(bm + row) * DDIM + k0 + lseg * 8);
            cp_async16(sBu[buf] + so, Bs + (size_t)(bn + row) * DDIM + k0 + lseg * 8);
        }
        cp_commit();
    };

    issue(0);
    for (int cc = 0; cc < NCHUNK; ++cc) {
        if (cc + 1 < NCHUNK) { issue(cc + 1); cp_wait<1>(); }
        else                 { cp_wait<0>(); }
        __syncthreads();

        int buf = cc & 1;
        uint32_t aB = sAu[buf], bB = sBu[buf];
#pragma unroll
        for (int kk2 = 0; kk2 < 2; kk2++) {     // k16 halves of the 32-chunk
            uint32_t afr[2][4], bfr[4][4];
            uint32_t colb = (uint32_t)(kk2 * 16 + (lane >> 4) * 8) * 2;
#pragma unroll
            for (int mi = 0; mi < 2; mi++) {
                uint32_t addr = aB + (uint32_t)((wm * 32 + mi * 16 + (lane & 15)) * ROWH) * 2 + colb;
                ldm_x4(afr[mi], addr);
            }
#pragma unroll
            for (int ni = 0; ni < 4; ni++) {
                uint32_t addr = bB + (uint32_t)((wn * 64 + ni * 16 + (lane & 15)) * ROWH) * 2 + colb;
                ldm_x4(bfr[ni], addr);
            }
#pragma unroll
            for (int mi = 0; mi < 2; mi++)
#pragma unroll
                for (int nj = 0; nj < 8; nj++) {
                    int ni = nj >> 1, h2 = nj & 1;
                    mma16816(acc[mi][nj], afr[mi], bfr[ni][h2], bfr[ni][h2 + 2]);
                }
        }
        // undo residual scaling at pass boundaries
        if (cc == 15 || cc == 47) {
#pragma unroll
            for (int mi = 0; mi < 2; mi++)
#pragma unroll
                for (int nj = 0; nj < 8; nj++)
#pragma unroll
                    for (int q = 0; q < 4; q++) acc[mi][nj][q] *= INVLOSCALE;
        }
        __syncthreads();
    }

    // ---- epilogue: direct float2 stores with bias ----
    int rbase = bm + wm * 32 + (lane >> 2);
    int cb    = bn + wn * 64 + 2 * (lane & 3);
#pragma unroll
    for (int mi = 0; mi < 2; mi++) {
#pragma unroll
        for (int nj = 0; nj < 8; nj++) {
            int col = cb + nj * 8;
            float bx = bias[col], by = bias[col + 1];
            float2 v0 = make_float2(acc[mi][nj][0] + bx, acc[mi][nj][1] + by);
            float2 v1 = make_float2(acc[mi][nj][2] + bx, acc[mi][nj][3] + by);
            int r0 = rbase + mi * 16;
            *(float2*)(C + (size_t)r0 * DDIM + col)       = v0;
            *(float2*)(C + (size_t)(r0 + 8) * DDIM + col) = v1;
        }
    }
}

// ---------------- fused attention: one CTA per (b,h) ----------------
#define SMEM_ATTN ((128 * 129 + 128 * 64) * 4)

__global__ void __launch_bounds__(128) attn_kernel(
    const float* __restrict__ corr,
    const float* __restrict__ fimp)
{
    extern __shared__ float sm[];
    float*    sc  = sm;                       // 128*129 (keys / probs)
    unsigned* scu = (unsigned*)sm;
    float*    kv  = sm + 128 * 129;           // 128*64 (k tile, then v tile)

    int bh = blockIdx.x;
    int b = bh >> 3, h = bh & 7;
    int r = threadIdx.x;

    const float* qbase = g_qkv + (size_t)b * FDIM * DDIM + h * HD;
    const float* kbase = qbase + (size_t)MTOT * DDIM;
    const float* vbase = qbase + (size_t)2 * MTOT * DDIM;

    // K tile: rows f, head slice (stride DDIM)
    for (int i = r; i < 2048; i += 128) {
        int row = i >> 4, seg = i & 15;
        *(float4*)(kv + row * 64 + seg * 4) =
            *(const float4*)(kbase + (size_t)row * DDIM + seg * 4);
    }
    // q row in registers
    float4 qv[16];
    const float4* qp = (const float4*)(qbase + (size_t)r * DDIM);
#pragma unroll
    for (int d = 0; d < 16; d++) qv[d] = qp[d];
    __syncthreads();

    float fi_r = fimp[r];
    float pvh  = g_pv[b] * 0.5f;
    bool  rlo  = (r < 64);
    const float* crow = corr + r * FDIM;
    unsigned* srow = scu + r * 129;

    for (int j = 0; j < FDIM; j++) {
        const float4* kp = (const float4*)(kv + j * 64);
        float a0 = 0.f, a1 = 0.f, a2 = 0.f, a3 = 0.f;
#pragma unroll
        for (int d = 0; d < 16; d++) {
            float4 kk = kp[d];
            a0 += qv[d].x * kk.x; a1 += qv[d].y * kk.y;
            a2 += qv[d].z * kk.z; a3 += qv[d].w * kk.w;
        }
        float s = ((a0 + a1) + (a2 + a3)) * 0.125f + crow[j] * fi_r * fimp[j];
        if (rlo != (j < 64)) s += pvh;
        srow[j] = f2k(s);
    }
    __syncthreads();   // everyone done reading K

    // overwrite kv with V tile
    for (int i = r; i < 2048; i += 128) {
        int row = i >> 4, seg = i & 15;
        *(float4*)(kv + row * 64 + seg * 4) =
            *(const float4*)(vbase + (size_t)row * DDIM + seg * 4);
    }

    // exact 64th-largest via MSB-first radix select
    unsigned prefix = 0u;
    int kk = KTOP;
    for (int bit = 31; bit >= 0; --bit) {
        unsigned want = (prefix >> bit) | 1u;
        int c = 0;
#pragma unroll 4
        for (int j = 0; j < FDIM; j++) c += (int)((srow[j] >> bit) == want);
        if (c >= kk) prefix |= (1u << bit); else kk -= c;
    }

    unsigned umax = 0u;
#pragma unroll 4
    for (int j = 0; j < FDIM; j++) umax = max(umax, srow[j]);
    float m = k2f(umax);

    float ssum = 0.f;
    float* frow = sc + r * 129;
    for (int j = 0; j < FDIM; j++) {
        unsigned key = srow[j];
        float e = (key >= prefix) ? __expf(k2f(key) - m) : 0.f;
        frow[j] = e;
        ssum += e;
    }
    float inv = 1.f / ssum;

    __syncthreads();   // V tile fully loaded

    float4 acc4[16];
#pragma unroll
    for (int d = 0; d < 16; d++) acc4[d] = make_float4(0.f, 0.f, 0.f, 0.f);
    for (int j = 0; j < FDIM; j++) {
        float e = frow[j];
        const float4* vp = (const float4*)(kv + j * 64);
#pragma unroll
        for (int d = 0; d < 16; d++) {
            float4 vv = vp[d];
            acc4[d].x += e * vv.x; acc4[d].y += e * vv.y;
            acc4[d].z += e * vv.z; acc4[d].w += e * vv.w;
        }
    }

    float* obase = g_attn + ((size_t)b * FDIM + r) * DDIM + h * HD;
#pragma unroll
    for (int d = 0; d < 16; d++) {
        float4 t;
        t.x = acc4[d].x * inv; t.y = acc4[d].y * inv;
        t.z = acc4[d].z * inv; t.w = acc4[d].w * inv;
        *(float4*)(obase + d * 4) = t;
    }
}

// ---------------- launch ----------------
extern "C" void kernel_launch(void* const* d_in, const int* in_sizes, int n_in,
                              void* d_out, int out_size)
{
    const float* x    = (const float*)d_in[0];
    const float* Wq   = (const float*)d_in[1];
    const float* bq   = (const float*)d_in[2];
    const float* Wk   = (const float*)d_in[3];
    const float* bk   = (const float*)d_in[4];
    const float* Wv   = (const float*)d_in[5];
    const float* bv   = (const float*)d_in[6];
    const float* Wo   = (const float*)d_in[7];
    const float* bo   = (const float*)d_in[8];
    const float* corr = (const float*)d_in[9];
    const float* fimp = (const float*)d_in[10];
    const float* W1   = (const float*)d_in[11];
    const float* b1   = (const float*)d_in[12];
    const float* W2   = (const float*)d_in[13];
    const float* b2   = (const float*)d_in[14];
    float* out = (float*)d_out;

    cudaFuncSetAttribute(attn_kernel, cudaFuncAttributeMaxDynamicSharedMemorySize, SMEM_ATTN);

    // prep: fp16 hi/lo splits of x and transposed weights
    split_kernel<<<16384, 256>>>((const float4*)x, 0);
    wsplit_kernel<<<dim3(16, 16, 4), dim3(32, 32)>>>(Wq, Wk, Wv, Wo);
    pv_kernel<<<BSZ, 256>>>(x, W1, b1, W2, b2);

    // q,k,v projections on tensor cores (HMMA, 4-term split)
    gemm_mma<<<dim3(4, 256, 3), 256>>>(0, bq, bk, bv, nullptr);

    // fused sparse attention
    attn_kernel<<<BSZ * HH, 128, SMEM_ATTN>>>(corr, fimp);

    // output projection on tensor cores
    split_kernel<<<16384, 256>>>(nullptr, 1);
    gemm_mma<<<dim3(4, 256, 1), 256>>>(1, bo, bo, bo, out);
}

// round 7
// speedup vs baseline: 1.6389x; 1.2052x over previous
#include <cuda_runtime.h>
#include <cuda_fp16.h>
#include <cstdint>

#define BSZ  256
#define FDIM 128
#define DDIM 512
#define HH   8
#define HD   64
#define KTOP 64
#define MTOT (BSZ * FDIM)            // 32768
#define LOSCALE 2048.0f
#define INVLOSCALE (1.0f / 2048.0f)

// ---------------- scratch (device globals: allocation-free) ----------------
__device__ float g_qkv[(size_t)3 * MTOT * DDIM];   // q,k,v in (B,F,D) plain layout
__device__ float g_pv[BSZ];
__device__ __half g_xhi[(size_t)MTOT * DDIM];
__device__ __half g_xlo[(size_t)MTOT * DDIM];      // scaled by 2048
__device__ __half g_ahi[(size_t)MTOT * DDIM];      // attn out hi (written by attn_kernel)
__device__ __half g_alo[(size_t)MTOT * DDIM];      // attn out lo (scaled by 2048)
__device__ __half g_wthi[(size_t)4 * DDIM * DDIM]; // W^T (n,k) for q,k,v,o
__device__ __half g_wtlo[(size_t)4 * DDIM * DDIM]; // scaled by 2048

// ---------------- helpers ----------------
typedef unsigned long long u64c;

__device__ __forceinline__ uint32_t smem_u32(const void* p) {
    uint32_t a;
    asm("{ .reg .u64 t; cvta.to.shared.u64 t, %1; cvt.u32.u64 %0, t; }" : "=r"(a) : "l"(p));
    return a;
}
__device__ __forceinline__ void cp_async16(uint32_t dst, const void* src) {
    asm volatile("cp.async.cg.shared.global [%0], [%1], 16;" :: "r"(dst), "l"(src) : "memory");
}
__device__ __forceinline__ void cp_commit() {
    asm volatile("cp.async.commit_group;" ::: "memory");
}
template<int N>
__device__ __forceinline__ void cp_wait() {
    asm volatile("cp.async.wait_group %0;" :: "n"(N) : "memory");
}
__device__ __forceinline__ void ldm_x4(uint32_t* r, uint32_t addr) {
    asm volatile("ldmatrix.sync.aligned.m8n8.x4.shared.b16 {%0,%1,%2,%3}, [%4];"
                 : "=r"(r[0]), "=r"(r[1]), "=r"(r[2]), "=r"(r[3]) : "r"(addr));
}
__device__ __forceinline__ void mma16816(float* c, const uint32_t* a, uint32_t b0, uint32_t b1) {
    asm volatile(
        "mma.sync.aligned.m16n8k16.row.col.f32.f16.f16.f32 "
        "{%0,%1,%2,%3}, {%4,%5,%6,%7}, {%8,%9}, {%0,%1,%2,%3};"
        : "+f"(c[0]), "+f"(c[1]), "+f"(c[2]), "+f"(c[3])
        : "r"(a[0]), "r"(a[1]), "r"(a[2]), "r"(a[3]), "r"(b0), "r"(b1));
}
// packed f32x2 ops (sm_100+ base ISA)
__device__ __forceinline__ u64c pk2(float a, float b) {
    u64c r; asm("mov.b64 %0, {%1, %2};" : "=l"(r) : "f"(a), "f"(b)); return r;
}
__device__ __forceinline__ void upk2(float& a, float& b, u64c v) {
    asm("mov.b64 {%0, %1}, %2;" : "=f"(a), "=f"(b) : "l"(v));
}
__device__ __forceinline__ void fma2(u64c& d, u64c a, u64c b) {
    asm("fma.rn.f32x2 %0, %1, %2, %0;" : "+l"(d) : "l"(a), "l"(b));
}

// monotone float<->uint key mapping (larger key <=> larger float)
__device__ __forceinline__ unsigned f2k(float f) {
    unsigned u = __float_as_uint(f);
    return (u & 0x80000000u) ? ~u : (u | 0x80000000u);
}
__device__ __forceinline__ float k2f(unsigned k) {
    unsigned u = (k & 0x80000000u) ? (k ^ 0x80000000u) : ~k;
    return __uint_as_float(u);
}

// ---------------- fp16 hi/lo split of x (lo scaled by 2048) ----------------
__global__ void __launch_bounds__(256) split_kernel(const float4* __restrict__ xsrc) {
    size_t i = (size_t)blockIdx.x * 256 + threadIdx.x;   // grid sized exactly
    __half2* hi = (__half2*)g_xhi;
    __half2* lo = (__half2*)g_xlo;
    float4 v = xsrc[i];
    __half hx = __float2half(v.x), hy = __float2half(v.y);
    __half hz = __float2half(v.z), hw = __float2half(v.w);
    __half2 h0; h0.x = hx; h0.y = hy;
    __half2 h1; h1.x = hz; h1.y = hw;
    __half2 l0, l1;
    l0.x = __float2half((v.x - __half2float(hx)) * LOSCALE);
    l0.y = __float2half((v.y - __half2float(hy)) * LOSCALE);
    l1.x = __float2half((v.z - __half2float(hz)) * LOSCALE);
    l1.y = __float2half((v.w - __half2float(hw)) * LOSCALE);
    hi[2 * i] = h0; hi[2 * i + 1] = h1;
    lo[2 * i] = l0; lo[2 * i + 1] = l1;
}

// ---------------- weight transpose + split: W[k][n] -> Wt[n][k] hi/lo ----------------
__global__ void wsplit_kernel(const float* __restrict__ Wq, const float* __restrict__ Wk,
                              const float* __restrict__ Wv, const float* __restrict__ Wo) {
    int z = blockIdx.z;
    const float* W = (z == 0) ? Wq : (z == 1) ? Wk : (z == 2) ? Wv : Wo;
    __shared__ float t[32][33];
    int n0 = blockIdx.x * 32, k0 = blockIdx.y * 32;
    int tx = threadIdx.x, ty = threadIdx.y;
    t[ty][tx] = W[(size_t)(k0 + ty) * DDIM + n0 + tx];
    __syncthreads();
    float v = t[tx][ty];                      // = W[k0+tx][n0+ty]
    __half h = __float2half(v);
    size_t o = (size_t)z * DDIM * DDIM + (size_t)(n0 + ty) * DDIM + k0 + tx;
    g_wthi[o] = h;
    g_wtlo[o] = __float2half((v - __half2float(h)) * LOSCALE);
}

// ---------------- pv gating MLP: one block per batch ----------------
__global__ void __launch_bounds__(256) pv_kernel(
    const float* __restrict__ x,
    const float* __restrict__ W1, const float* __restrict__ b1,
    const float* __restrict__ W2, const float* __restrict__ b2)
{
    int b = blockIdx.x;
    int tid = threadIdx.x;
    __shared__ float comb[1024];
    __shared__ float red[256];

    for (int d = tid; d < DDIM; d += 256) {
        float s1 = 0.f, s2 = 0.f;
        const float* xb = x + (size_t)b * FDIM * DDIM;
        for (int f = 0; f < 64; f++)   s1 += xb[f * DDIM + d];
        for (int f = 64; f < 128; f++) s2 += xb[f * DDIM + d];
        comb[d]       = s1 * (1.f / 64.f);
        comb[512 + d] = s2 * (1.f / 64.f);
    }
    __syncthreads();

    float part = 0.f;
    for (int j = tid; j < DDIM; j += 256) {
        float acc = b1[j];
        for (int i = 0; i < 1024; i++) acc += comb[i] * W1[i * DDIM + j];
        float hsil = acc / (1.f + __expf(-acc));
        part += hsil * W2[j];
    }
    red[tid] = part;
    for (int s = 128; s > 0; s >>= 1) {
        __syncthreads();
        if (tid < s) red[tid] += red[tid + s];
    }
    __syncthreads();
    if (tid == 0) {
        float z = red[0] + b2[0];
        g_pv[b] = 1.f / (1.f + __expf(-z));
    }
}

// ---------------- HMMA fp16 3-term split GEMM: C[M,512] = A[M,512] @ W + bias ----------------
// Virtual K' = 3*512 with scaled residuals (lo' = lo*2048):
//   chunks  0-15 : Ahi *Blo'  \  both cross terms at 2^11 scale
//   chunks 16-31 : Alo'*Bhi   /
//   rescale acc *= 2^-11
//   chunks 32-47 : Ahi *Bhi
// (lo*lo term dropped: 2^-22 relative, below fp32 accumulation noise)
// CTA: 128x128, 8 warps of 32x64. K-chunk 32, 4-stage cp.async, 1 sync/chunk.
#define KC      32
#define ROWH    40
#define NCHUNK  48
#define NSTAGE  4
#define TILE_HALF (128 * ROWH)                        // 5120 halves = 10240 B
#define GEMM_SMEM (NSTAGE * TILE_HALF * 2 * 2)        // 81920 bytes

__global__ void __launch_bounds__(256, 2) gemm_mma(
    int mode,
    const float* __restrict__ b0, const float* __restrict__ b1, const float* __restrict__ b2,
    float* __restrict__ Cout)
{
    extern __shared__ __half gsm[];
    __half* sA = gsm;
    __half* sB = gsm + NSTAGE * TILE_HALF;

    int tid  = threadIdx.x;
    int lane = tid & 31;
    int wid  = tid >> 5;
    int wm   = wid & 3;          // 0..3 -> M offset 32*wm
    int wn   = wid >> 2;         // 0..1 -> N offset 64*wn
    int z    = blockIdx.z;

    const __half* Ahi = mode ? g_ahi : g_xhi;
    const __half* Alo = mode ? g_alo : g_xlo;
    int wz = mode ? 3 : z;
    const __half* Bhi = g_wthi + (size_t)wz * DDIM * DDIM;
    const __half* Blo = g_wtlo + (size_t)wz * DDIM * DDIM;
    const float* bias = (z == 0) ? b0 : (z == 1) ? b1 : b2;
    float* C = mode ? Cout : (g_qkv + (size_t)z * MTOT * DDIM);

    int bm = blockIdx.y * 128;
    int bn = blockIdx.x * 128;

    int lrow0 = tid >> 2;              // 0..63
    int lseg  = tid & 3;               // 16B segment within 64B row-chunk

    float acc[2][8][4];
#pragma unroll
    for (int mi = 0; mi < 2; mi++)
#pragma unroll
        for (int nj = 0; nj < 8; nj++)
#pragma unroll
            for (int q = 0; q < 4; q++) acc[mi][nj][q] = 0.f;

    uint32_t sAu = smem_u32(sA);
    uint32_t sBu = smem_u32(sB);

    // ---- issue loads for a chunk ----
    auto issue = [&](int cc) {
        int p  = cc >> 4;                      // 0: hi*lo', 1: lo'*hi, 2: hi*hi
        int k0 = (cc & 15) * KC;
        const __half* As = (p == 1) ? Alo : Ahi;
        const __half* Bs = (p == 0) ? Blo : Bhi;
        uint32_t base = (uint32_t)(cc & (NSTAGE - 1)) * TILE_HALF * 2;
#pragma unroll
        for (int r = 0; r < 2; r++) {
            int row = lrow0 + r * 64;
            uint32_t so = base + (uint32_t)(row * ROWH + lseg * 8) * 2;
            cp_async16(sAu + so, As + (size_t)(bm + row) * DDIM + k0 + lseg * 8);
            cp_async16(sBu + so, Bs + (size_t)(bn + row) * DDIM + k0 + lseg * 8);
        }
        cp_commit();
    };

#pragma unroll
    for (int i = 0; i < NSTAGE - 1; i++) issue(i);

    for (int cc = 0; cc < NCHUNK; ++cc) {
        cp_wait<NSTAGE - 2>();
        __syncthreads();
        if (cc + NSTAGE - 1 < NCHUNK) issue(cc + NSTAGE - 1);
        else                          cp_commit();          // keep group count uniform

        uint32_t base = (uint32_t)(cc & (NSTAGE - 1)) * TILE_HALF * 2;
        uint32_t aB = sAu + base, bB = sBu + base;
#pragma unroll
        for (int kk2 = 0; kk2 < 2; kk2++) {     // k16 halves of the 32-chunk
            uint32_t afr[2][4], bfr[4][4];
            uint32_t colb = (uint32_t)(kk2 * 16 + (lane >> 4) * 8) * 2;
#pragma unroll
            for (int mi = 0; mi < 2; mi++) {
                uint32_t addr = aB + (uint32_t)((wm * 32 + mi * 16 + (lane & 15)) * ROWH) * 2 + colb;
                ldm_x4(afr[mi], addr);
            }
#pragma unroll
            for (int ni = 0; ni < 4; ni++) {
                uint32_t addr = bB + (uint32_t)((wn * 64 + ni * 16 + (lane & 15)) * ROWH) * 2 + colb;
                ldm_x4(bfr[ni], addr);
            }
#pragma unroll
            for (int mi = 0; mi < 2; mi++)
#pragma unroll
                for (int nj = 0; nj < 8; nj++) {
                    int ni = nj >> 1, h2 = nj & 1;
                    mma16816(acc[mi][nj], afr[mi], bfr[ni][h2], bfr[ni][h2 + 2]);
                }
        }
        // undo residual scaling once, after both cross-term passes
        if (cc == 31) {
#pragma unroll
            for (int mi = 0; mi < 2; mi++)
#pragma unroll
                for (int nj = 0; nj < 8; nj++)
#pragma unroll
                    for (int q = 0; q < 4; q++) acc[mi][nj][q] *= INVLOSCALE;
        }
    }

    // ---- epilogue: direct float2 stores with bias ----
    int rbase = bm + wm * 32 + (lane >> 2);
    int cb    = bn + wn * 64 + 2 * (lane & 3);
#pragma unroll
    for (int mi = 0; mi < 2; mi++) {
#pragma unroll
        for (int nj = 0; nj < 8; nj++) {
            int col = cb + nj * 8;
            float bx = bias[col], by = bias[col + 1];
            float2 v0 = make_float2(acc[mi][nj][0] + bx, acc[mi][nj][1] + by);
            float2 v1 = make_float2(acc[mi][nj][2] + bx, acc[mi][nj][3] + by);
            int r0 = rbase + mi * 16;
            *(float2*)(C + (size_t)r0 * DDIM + col)       = v0;
            *(float2*)(C + (size_t)(r0 + 8) * DDIM + col) = v1;
        }
    }
}

// ---------------- fused attention: one CTA per (b,h) ----------------
// f32x2 packed math in scores + AV; writes hi/lo fp16 split directly.
#define SMEM_ATTN ((128 * 129 + 128 * 64) * 4)

__global__ void __launch_bounds__(128) attn_kernel(
    const float* __restrict__ corr,
    const float* __restrict__ fimp)
{
    extern __shared__ float sm[];
    unsigned* scu = (unsigned*)sm;            // 128*129 keys
    float*    kv  = sm + 128 * 129;           // 128*64 (k tile, then v tile)

    int bh = blockIdx.x;
    int b = bh >> 3, h = bh & 7;
    int r = threadIdx.x;

    const float* qbase = g_qkv + (size_t)b * FDIM * DDIM + h * HD;
    const float* kbase = qbase + (size_t)MTOT * DDIM;
    const float* vbase = qbase + (size_t)2 * MTOT * DDIM;

    // K tile: rows f, head slice (stride DDIM)
    for (int i = r; i < 2048; i += 128) {
        int row = i >> 4, seg = i & 15;
        *(float4*)(kv + row * 64 + seg * 4) =
            *(const float4*)(kbase + (size_t)row * DDIM + seg * 4);
    }
    // q row packed into f32x2 registers
    u64c qv2[32];
    const float4* qp = (const float4*)(qbase + (size_t)r * DDIM);
#pragma unroll
    for (int d = 0; d < 16; d++) {
        float4 t = qp[d];
        qv2[2 * d]     = pk2(t.x, t.y);
        qv2[2 * d + 1] = pk2(t.z, t.w);
    }
    __syncthreads();

    float fi_r = fimp[r];
    float pvh  = g_pv[b] * 0.5f;
    bool  rlo  = (r < 64);
    const float* crow = corr + r * FDIM;
    unsigned* srow = scu + r * 129;

    for (int j = 0; j < FDIM; j++) {
        const ulonglong2* kp = (const ulonglong2*)(kv + j * HD);
        u64c c0 = 0, c1 = 0, c2 = 0, c3 = 0;
#pragma unroll
        for (int d = 0; d < 16; d += 2) {
            ulonglong2 t0 = kp[d], t1 = kp[d + 1];
            fma2(c0, qv2[2 * d],     t0.x);
            fma2(c1, qv2[2 * d + 1], t0.y);
            fma2(c2, qv2[2 * d + 2], t1.x);
            fma2(c3, qv2[2 * d + 3], t1.y);
        }
        float x0, x1, y0, y1, z0, z1, w0, w1;
        upk2(x0, x1, c0); upk2(y0, y1, c1); upk2(z0, z1, c2); upk2(w0, w1, c3);
        float s = (((x0 + x1) + (y0 + y1)) + ((z0 + z1) + (w0 + w1))) * 0.125f
                + crow[j] * fi_r * fimp[j];
        if (rlo != (j < 64)) s += pvh;
        srow[j] = f2k(s);
    }
    __syncthreads();   // everyone done reading K

    // overwrite kv with V tile
    for (int i = r; i < 2048; i += 128) {
        int row = i >> 4, seg = i & 15;
        *(float4*)(kv + row * 64 + seg * 4) =
            *(const float4*)(vbase + (size_t)row * DDIM + seg * 4);
    }

    // exact 64th-largest via MSB-first radix select
    unsigned prefix = 0u;
    int kk = KTOP;
    for (int bit = 31; bit >= 0; --bit) {
        unsigned want = (prefix >> bit) | 1u;
        int c = 0;
#pragma unroll 4
        for (int j = 0; j < FDIM; j++) c += (int)((srow[j] >> bit) == want);
        if (c >= kk) prefix |= (1u << bit); else kk -= c;
    }

    unsigned umax = 0u;
#pragma unroll 4
    for (int j = 0; j < FDIM; j++) umax = max(umax, srow[j]);
    float m = k2f(umax);

    __syncthreads();   // V tile fully loaded

    // single pass: exp + sum + AV accumulate (packed f32x2)
    u64c av[32];
#pragma unroll
    for (int d = 0; d < 32; d++) av[d] = 0ull;
    float ssum = 0.f;
    for (int j = 0; j < FDIM; j++) {
        unsigned key = srow[j];
        float e = (key >= prefix) ? __expf(k2f(key) - m) : 0.f;
        ssum += e;
        u64c e2 = pk2(e, e);
        const ulonglong2* vp = (const ulonglong2*)(kv + j * HD);
#pragma unroll
        for (int d = 0; d < 16; d++) {
            ulonglong2 t = vp[d];
            fma2(av[2 * d],     e2, t.x);
            fma2(av[2 * d + 1], e2, t.y);
        }
    }
    float inv = 1.f / ssum;

    // epilogue: normalize + fp16 hi/lo split, store directly for out-projection
    size_t obase = ((size_t)b * FDIM + r) * DDIM + h * HD;
    __half2* hi2 = (__half2*)(g_ahi + obase);
    __half2* lo2 = (__half2*)(g_alo + obase);
#pragma unroll
    for (int d = 0; d < 32; d++) {
        float a, bb2;
        upk2(a, bb2, av[d]);
        a *= inv; bb2 *= inv;
        __half ha = __float2half(a), hb = __float2half(bb2);
        hi2[d] = __halves2half2(ha, hb);
        lo2[d] = __halves2half2(__float2half((a   - __half2float(ha)) * LOSCALE),
                                __float2half((bb2 - __half2float(hb)) * LOSCALE));
    }
}

// ---------------- launch ----------------
extern "C" void kernel_launch(void* const* d_in, const int* in_sizes, int n_in,
                              void* d_out, int out_size)
{
    const float* x    = (const float*)d_in[0];
    const float* Wq   = (const float*)d_in[1];
    const float* bq   = (const float*)d_in[2];
    const float* Wk   = (const float*)d_in[3];
    const float* bk   = (const float*)d_in[4];
    const float* Wv   = (const float*)d_in[5];
    const float* bv   = (const float*)d_in[6];
    const float* Wo   = (const float*)d_in[7];
    const float* bo   = (const float*)d_in[8];
    const float* corr = (const float*)d_in[9];
    const float* fimp = (const float*)d_in[10];
    const float* W1   = (const float*)d_in[11];
    const float* b1   = (const float*)d_in[12];
    const float* W2   = (const float*)d_in[13];
    const float* b2   = (const float*)d_in[14];
    float* out = (float*)d_out;

    cudaFuncSetAttribute(gemm_mma, cudaFuncAttributeMaxDynamicSharedMemorySize, GEMM_SMEM);
    cudaFuncSetAttribute(attn_kernel, cudaFuncAttributeMaxDynamicSharedMemorySize, SMEM_ATTN);

    // prep: fp16 hi/lo splits of x and transposed weights
    split_kernel<<<16384, 256>>>((const float4*)x);
    wsplit_kernel<<<dim3(16, 16, 4), dim3(32, 32)>>>(Wq, Wk, Wv, Wo);
    pv_kernel<<<BSZ, 256>>>(x, W1, b1, W2, b2);

    // q,k,v projections on tensor cores (HMMA, 3-term split, 4-stage pipeline)
    gemm_mma<<<dim3(4, 256, 3), 256, GEMM_SMEM>>>(0, bq, bk, bv, nullptr);

    // fused sparse attention (writes hi/lo split output directly)
    attn_kernel<<<BSZ * HH, 128, SMEM_ATTN>>>(corr, fimp);

    // output projection on tensor cores
    gemm_mma<<<dim3(4, 256, 1), 256, GEMM_SMEM>>>(1, bo, bo, bo, out);
}